// round 2
// baseline (speedup 1.0000x reference)
#include <cuda_runtime.h>

typedef unsigned long long u64;

#define NTHREADS 256
#define GRID_BLOCKS 2048   // 1048576 elems / (2 per thread * 256)

// ---------- packed f32x2 + approx-math helpers ----------
__device__ __forceinline__ u64 f2fma(u64 a, u64 b, u64 c) {
    u64 d; asm("fma.rn.f32x2 %0, %1, %2, %3;" : "=l"(d) : "l"(a), "l"(b), "l"(c)); return d;
}
__device__ __forceinline__ u64 pk2(float lo, float hi) {
    u64 d; asm("mov.b64 %0, {%1,%2};" : "=l"(d) : "f"(lo), "f"(hi)); return d;
}
__device__ __forceinline__ void up2(u64 a, float& lo, float& hi) {
    asm("mov.b64 {%0,%1}, %2;" : "=f"(lo), "=f"(hi) : "l"(a));
}
__device__ __forceinline__ float ex2f(float x) {
    float y; asm("ex2.approx.f32 %0, %1;" : "=f"(y) : "f"(x)); return y;
}
__device__ __forceinline__ float rcpf(float x) {
    float y; asm("rcp.approx.f32 %0, %1;" : "=f"(y) : "f"(x)); return y;
}

// sigmoid(x) = 1 / (1 + 2^(-x*log2e))
__device__ __forceinline__ u64 sigmoid2(u64 g) {
    float lo, hi; up2(g, lo, hi);
    float el = ex2f(-1.4426950408889634f * lo);
    float eh = ex2f(-1.4426950408889634f * hi);
    return pk2(rcpf(1.0f + el), rcpf(1.0f + eh));
}
// tanh(x) = 2 / (1 + 2^(-2x*log2e)) - 1
__device__ __forceinline__ u64 tanh2(u64 g) {
    float lo, hi; up2(g, lo, hi);
    float el = ex2f(-2.8853900817779268f * lo);
    float eh = ex2f(-2.8853900817779268f * hi);
    float rl = rcpf(1.0f + el), rh = rcpf(1.0f + eh);
    return pk2(fmaf(2.0f, rl, -1.0f), fmaf(2.0f, rh, -1.0f));
}

// ---------- kernel ----------
// B=1048576, T=4, I=2, H=16
// out layout: [hidden_table B*T*H][sum_logits B*T][carry B][output_logits B*5]

__global__ __launch_bounds__(NTHREADS)
void gru_adder_kernel(const float* __restrict__ x,
                      const float* __restrict__ wih,   // [48,2]
                      const float* __restrict__ whh,   // [48,16]
                      const float* __restrict__ bih,   // [48]
                      const float* __restrict__ bhh,   // [48]
                      const float* __restrict__ wsum,  // [1,16]
                      const float* __restrict__ bsum,  // [1]
                      const float* __restrict__ wcar,  // [1,16]
                      const float* __restrict__ bcar,  // [1]
                      float* __restrict__ out)
{
    // Weights staged in shared, each scalar duplicated into a (w,w) 64-bit pair
    // so an f32x2 FMA can consume it directly from an LDS.128 broadcast.
    __shared__ __align__(16) u64 s_wih[96];    // [j][i] dup
    __shared__ __align__(16) u64 s_whh[768];   // [j][k] dup, row = 16 u64 = 128B
    __shared__ __align__(16) u64 s_brz[32];    // b_ih + b_hh for r,z gates
    __shared__ __align__(16) u64 s_bin[16];    // b_ih (n gate)
    __shared__ __align__(16) u64 s_bhn[16];    // b_hh (n gate)
    __shared__ __align__(16) u64 s_wsum[16];
    __shared__ __align__(16) u64 s_wcar[16];
    __shared__ __align__(16) u64 s_bs[2];      // [bsum, bcarry]

    const int tid = threadIdx.x;
    for (int i = tid; i < 96;  i += NTHREADS) { float v = wih[i]; s_wih[i] = pk2(v, v); }
    for (int i = tid; i < 768; i += NTHREADS) { float v = whh[i]; s_whh[i] = pk2(v, v); }
    if (tid < 32) {
        float v = bih[tid] + bhh[tid]; s_brz[tid] = pk2(v, v);
    } else if (tid < 48) {
        int k = tid - 32;
        float a = bih[32 + k]; s_bin[k] = pk2(a, a);
        float b = bhh[32 + k]; s_bhn[k] = pk2(b, b);
    } else if (tid < 64) {
        int k = tid - 48;
        float a = wsum[k]; s_wsum[k] = pk2(a, a);
        float b = wcar[k]; s_wcar[k] = pk2(b, b);
    } else if (tid == 64) {
        s_bs[0] = pk2(bsum[0], bsum[0]);
        s_bs[1] = pk2(bcar[0], bcar[0]);
    }
    __syncthreads();

    const size_t gt = (size_t)blockIdx.x * NTHREADS + tid;  // pair index
    const size_t b0 = 2 * gt;                                // even batch elem; b1 = b0+1

    // x for both elems: 2 * 8 contiguous floats = 64B contiguous per thread
    const float4* xp = (const float4*)(x + b0 * 8);
    float4 a0 = xp[0], a1 = xp[1], c0 = xp[2], c1 = xp[3];
    u64 px[4][2];
    px[0][0] = pk2(a0.x, c0.x); px[0][1] = pk2(a0.y, c0.y);
    px[1][0] = pk2(a0.z, c0.z); px[1][1] = pk2(a0.w, c0.w);
    px[2][0] = pk2(a1.x, c1.x); px[2][1] = pk2(a1.y, c1.y);
    px[3][0] = pk2(a1.z, c1.z); px[3][1] = pk2(a1.w, c1.w);

    u64 h[16];
#pragma unroll
    for (int k = 0; k < 16; k++) h[k] = 0ull;   // 0 bits == (0.0f, 0.0f)

    u64 s[4];
    float* outH = out;
    float* outS = out + 67108864ULL;   // B*T*H
    float* outC = out + 71303168ULL;   // + B*T
    float* outO = out + 72351744ULL;   // + B
    const u64 NEG1 = 0xBF800000BF800000ull;  // (-1.0f, -1.0f)

#pragma unroll
    for (int t = 0; t < 4; t++) {
        // Pass 1: fused r+n. r_k is consumed immediately by n_k (never stored
        // as an array) — keeps peak live registers low, avoids local spill.
        u64 nv[16];
#pragma unroll
        for (int k = 0; k < 16; k++) {
            const int jr = k;        // r gate row
            const int jn = 32 + k;   // n gate row
            u64 ar = f2fma(px[t][0], s_wih[2 * jr],     s_brz[jr]);
            ar     = f2fma(px[t][1], s_wih[2 * jr + 1], ar);
            u64 iN = f2fma(px[t][0], s_wih[2 * jn],     s_bin[k]);
            iN     = f2fma(px[t][1], s_wih[2 * jn + 1], iN);
            u64 hN = s_bhn[k];
            const ulonglong2* wr = (const ulonglong2*)&s_whh[jr * 16];
            const ulonglong2* wn = (const ulonglong2*)&s_whh[jn * 16];
#pragma unroll
            for (int q = 0; q < 8; q++) {
                ulonglong2 w1 = wr[q];
                ulonglong2 w2 = wn[q];
                ar = f2fma(h[2 * q],     w1.x, ar);
                hN = f2fma(h[2 * q],     w2.x, hN);
                ar = f2fma(h[2 * q + 1], w1.y, ar);
                hN = f2fma(h[2 * q + 1], w2.y, hN);
            }
            nv[k] = tanh2(f2fma(sigmoid2(ar), hN, iN));
        }
        // Pass 2: z gates (all need OLD h, so must precede the update).
        u64 z[16];
#pragma unroll
        for (int k = 0; k < 16; k++) {
            const int j = 16 + k;
            u64 acc = f2fma(px[t][0], s_wih[2 * j],     s_brz[j]);
            acc     = f2fma(px[t][1], s_wih[2 * j + 1], acc);
            const ulonglong2* wr = (const ulonglong2*)&s_whh[j * 16];
#pragma unroll
            for (int q = 0; q < 8; q++) {
                ulonglong2 w = wr[q];
                acc = f2fma(h[2 * q],     w.x, acc);
                acc = f2fma(h[2 * q + 1], w.y, acc);
            }
            z[k] = sigmoid2(acc);
        }
        // h update + per-step sum logit
        u64 st = s_bs[0];
#pragma unroll
        for (int k = 0; k < 16; k++) {
            u64 d = f2fma(nv[k], NEG1, h[k]);   // h - n
            h[k]  = f2fma(z[k], d, nv[k]);      // n + z*(h-n) = (1-z)n + z h
            st    = f2fma(h[k], s_wsum[k], st);
        }
        s[t] = st;

        // store hidden_table rows for both elems (4x STG.128 each)
        float hl[16], hg[16];
#pragma unroll
        for (int k = 0; k < 16; k++) up2(h[k], hl[k], hg[k]);
        float4* p0 = (float4*)(outH + (b0 * 4 + (size_t)t) * 16);
        p0[0] = make_float4(hl[0],  hl[1],  hl[2],  hl[3]);
        p0[1] = make_float4(hl[4],  hl[5],  hl[6],  hl[7]);
        p0[2] = make_float4(hl[8],  hl[9],  hl[10], hl[11]);
        p0[3] = make_float4(hl[12], hl[13], hl[14], hl[15]);
        float4* p1 = (float4*)(outH + ((b0 + 1) * 4 + (size_t)t) * 16);
        p1[0] = make_float4(hg[0],  hg[1],  hg[2],  hg[3]);
        p1[1] = make_float4(hg[4],  hg[5],  hg[6],  hg[7]);
        p1[2] = make_float4(hg[8],  hg[9],  hg[10], hg[11]);
        p1[3] = make_float4(hg[12], hg[13], hg[14], hg[15]);
    }

    // carry logit from h_last
    u64 c = s_bs[1];
#pragma unroll
    for (int k = 0; k < 16; k++) c = f2fma(h[k], s_wcar[k], c);
    float cl, ch; up2(c, cl, ch);
    float sl[4], sg[4];
#pragma unroll
    for (int t = 0; t < 4; t++) up2(s[t], sl[t], sg[t]);

    // sum_logits [B,T]
    *(float4*)(outS + b0 * 4)       = make_float4(sl[0], sl[1], sl[2], sl[3]);
    *(float4*)(outS + (b0 + 1) * 4) = make_float4(sg[0], sg[1], sg[2], sg[3]);
    // carry [B,1]
    outC[b0]     = cl;
    outC[b0 + 1] = ch;
    // output_logits [B,5] — stride 5 not 16B-aligned -> scalar stores
    float* o0 = outO + b0 * 5;
    o0[0] = sl[0]; o0[1] = sl[1]; o0[2] = sl[2]; o0[3] = sl[3]; o0[4] = cl;
    float* o1 = outO + (b0 + 1) * 5;
    o1[0] = sg[0]; o1[1] = sg[1]; o1[2] = sg[2]; o1[3] = sg[3]; o1[4] = ch;
}

extern "C" void kernel_launch(void* const* d_in, const int* in_sizes, int n_in,
                              void* d_out, int out_size) {
    const float* x    = (const float*)d_in[0];
    const float* wih  = (const float*)d_in[1];
    const float* whh  = (const float*)d_in[2];
    const float* bih  = (const float*)d_in[3];
    const float* bhh  = (const float*)d_in[4];
    const float* wsum = (const float*)d_in[5];
    const float* bsum = (const float*)d_in[6];
    const float* wcar = (const float*)d_in[7];
    const float* bcar = (const float*)d_in[8];
    float* out = (float*)d_out;
    gru_adder_kernel<<<GRID_BLOCKS, NTHREADS>>>(x, wih, whh, bih, bhh,
                                                wsum, bsum, wcar, bcar, out);
}

// round 3
// speedup vs baseline: 1.2752x; 1.2752x over previous
#include <cuda_runtime.h>

typedef unsigned long long u64;

#define NTHREADS 256
#define GRID_BLOCKS 4096   // 1048576 elems / 256, one elem per thread

// ---------- packed f32x2 + approx-math helpers ----------
__device__ __forceinline__ u64 f2fma(u64 a, u64 b, u64 c) {
    u64 d; asm("fma.rn.f32x2 %0, %1, %2, %3;" : "=l"(d) : "l"(a), "l"(b), "l"(c)); return d;
}
__device__ __forceinline__ u64 pk2(float lo, float hi) {
    u64 d; asm("mov.b64 %0, {%1,%2};" : "=l"(d) : "f"(lo), "f"(hi)); return d;
}
__device__ __forceinline__ void up2(u64 a, float& lo, float& hi) {
    asm("mov.b64 {%0,%1}, %2;" : "=f"(lo), "=f"(hi) : "l"(a));
}
__device__ __forceinline__ float hsum(u64 a) {   // lo + hi
    float lo, hi; up2(a, lo, hi); return lo + hi;
}
__device__ __forceinline__ float ex2f(float x) {
    float y; asm("ex2.approx.f32 %0, %1;" : "=f"(y) : "f"(x)); return y;
}
__device__ __forceinline__ float rcpf(float x) {
    float y; asm("rcp.approx.f32 %0, %1;" : "=f"(y) : "f"(x)); return y;
}
__device__ __forceinline__ float sigmoidf_(float a) {
    return rcpf(1.0f + ex2f(-1.4426950408889634f * a));
}
__device__ __forceinline__ float tanhf_(float a) {
    return fmaf(2.0f, rcpf(1.0f + ex2f(-2.8853900817779268f * a)), -1.0f);
}

// ---------- kernel ----------
// B=1048576, T=4, I=2, H=16
// out layout: [hidden_table B*T*H][sum_logits B*T][carry B][output_logits B*5]

__global__ __launch_bounds__(NTHREADS)
void gru_adder_kernel(const float* __restrict__ x,
                      const float* __restrict__ wih,   // [48,2]
                      const float* __restrict__ whh,   // [48,16]
                      const float* __restrict__ bih,   // [48]
                      const float* __restrict__ bhh,   // [48]
                      const float* __restrict__ wsum,  // [1,16]
                      const float* __restrict__ bsum,  // [1]
                      const float* __restrict__ wcar,  // [1,16]
                      const float* __restrict__ bcar,  // [1]
                      float* __restrict__ out)
{
    // Weights in shared as (even,odd)-component f32x2 pairs.
    __shared__ __align__(16) u64   s_wih[48];      // (wih[j][0], wih[j][1])
    __shared__ __align__(16) u64   s_whh[384];     // [j][p] = (whh[j][2p], whh[j][2p+1]); row = 8 u64
    __shared__ __align__(16) u64   s_brz[32];      // (b_ih[j]+b_hh[j], 0) for r,z rows
    __shared__ __align__(16) u64   s_bin[16];      // (b_ih[32+k], 0)
    __shared__ __align__(16) u64   s_bhn[16];      // (b_hh[32+k], 0)
    __shared__            float s_wsum[16];
    __shared__            float s_wcar[16];
    __shared__            float s_bs[2];           // bsum, bcarry

    const int tid = threadIdx.x;
    if (tid < 48)  s_wih[tid] = pk2(wih[2 * tid], wih[2 * tid + 1]);
    if (tid < 32)  s_brz[tid] = pk2(bih[tid] + bhh[tid], 0.0f);
    if (tid >= 32 && tid < 48) {
        int k = tid - 32;
        s_bin[k] = pk2(bih[32 + k], 0.0f);
        s_bhn[k] = pk2(bhh[32 + k], 0.0f);
    }
    if (tid >= 48 && tid < 64) {
        int k = tid - 48;
        s_wsum[k] = wsum[k];
        s_wcar[k] = wcar[k];
    }
    if (tid == 64) { s_bs[0] = bsum[0]; s_bs[1] = bcar[0]; }
    for (int i = tid + 64; i < 384 + 64; i += NTHREADS) {
        int j = (i - 64) / 8, p = (i - 64) % 8;
        if (i - 64 < 384) s_whh[i - 64] = pk2(whh[j * 16 + 2 * p], whh[j * 16 + 2 * p + 1]);
    }
    __syncthreads();

    const size_t b = (size_t)blockIdx.x * NTHREADS + tid;  // one batch elem per thread

    // x: 8 contiguous floats (T=4, I=2) -> 2 LDG.128, px[t] = (x_t0, x_t1)
    const float4* xp = (const float4*)(x + b * 8);
    float4 xa = xp[0], xb = xp[1];
    u64 px0 = pk2(xa.x, xa.y);
    u64 px1 = pk2(xa.z, xa.w);
    u64 px2 = pk2(xb.x, xb.y);
    u64 px3 = pk2(xb.z, xb.w);

    u64 h[8];                         // (h0,h1),(h2,h3),...
#pragma unroll
    for (int p = 0; p < 8; p++) h[p] = 0ull;

    float* outH = out;
    float* outS = out + 67108864ULL;   // + B*T*H
    float* outC = out + 71303168ULL;   // + B*T
    float* outO = out + 72351744ULL;   // + B

    float sl[4];

#pragma unroll
    for (int t = 0; t < 4; t++) {
        const u64 pxt = (t == 0) ? px0 : (t == 1) ? px1 : (t == 2) ? px2 : px3;
        float hnf[16];
        float hf[16];
#pragma unroll
        for (int p = 0; p < 8; p++) up2(h[p], hf[2 * p], hf[2 * p + 1]);  // free (reg alias)

#pragma unroll
        for (int k = 0; k < 16; k++) {
            const int jr = k, jz = 16 + k, jn = 32 + k;
            u64 ar = f2fma(pxt, s_wih[jr], s_brz[jr]);
            u64 az = f2fma(pxt, s_wih[jz], s_brz[jz]);
            u64 iN = f2fma(pxt, s_wih[jn], s_bin[k]);
            u64 hN = s_bhn[k];
            const ulonglong2* wr = (const ulonglong2*)&s_whh[jr * 8];
            const ulonglong2* wz = (const ulonglong2*)&s_whh[jz * 8];
            const ulonglong2* wn = (const ulonglong2*)&s_whh[jn * 8];
#pragma unroll
            for (int q = 0; q < 4; q++) {
                ulonglong2 w1 = wr[q];
                ulonglong2 w2 = wz[q];
                ulonglong2 w3 = wn[q];
                ar = f2fma(h[2 * q],     w1.x, ar);
                az = f2fma(h[2 * q],     w2.x, az);
                hN = f2fma(h[2 * q],     w3.x, hN);
                ar = f2fma(h[2 * q + 1], w1.y, ar);
                az = f2fma(h[2 * q + 1], w2.y, az);
                hN = f2fma(h[2 * q + 1], w3.y, hN);
            }
            float r = sigmoidf_(hsum(ar));
            float z = sigmoidf_(hsum(az));
            float n = tanhf_(fmaf(r, hsum(hN), hsum(iN)));
            // h' = (1-z)n + z h = n + z*(h-n)
            hnf[k] = fmaf(z, hf[k] - n, n);
        }

        // commit h for next step (free: register repacking)
#pragma unroll
        for (int p = 0; p < 8; p++) h[p] = pk2(hnf[2 * p], hnf[2 * p + 1]);

        // per-step sum logit
        float st = s_bs[0];
#pragma unroll
        for (int k = 0; k < 16; k++) st = fmaf(hnf[k], s_wsum[k], st);
        sl[t] = st;

        // hidden_table row: 4x STG.128, fully coalesced within warp? strided by 64 floats
        float4* ph = (float4*)(outH + (b * 4 + (size_t)t) * 16);
        ph[0] = make_float4(hnf[0],  hnf[1],  hnf[2],  hnf[3]);
        ph[1] = make_float4(hnf[4],  hnf[5],  hnf[6],  hnf[7]);
        ph[2] = make_float4(hnf[8],  hnf[9],  hnf[10], hnf[11]);
        ph[3] = make_float4(hnf[12], hnf[13], hnf[14], hnf[15]);
    }

    // carry logit from h_last
    float c = s_bs[1];
    float hf[16];
#pragma unroll
    for (int p = 0; p < 8; p++) up2(h[p], hf[2 * p], hf[2 * p + 1]);
#pragma unroll
    for (int k = 0; k < 16; k++) c = fmaf(hf[k], s_wcar[k], c);

    // sum_logits [B,T]
    *(float4*)(outS + b * 4) = make_float4(sl[0], sl[1], sl[2], sl[3]);
    // carry [B,1]
    outC[b] = c;
    // output_logits [B,5]
    float* o = outO + b * 5;
    o[0] = sl[0]; o[1] = sl[1]; o[2] = sl[2]; o[3] = sl[3]; o[4] = c;
}

extern "C" void kernel_launch(void* const* d_in, const int* in_sizes, int n_in,
                              void* d_out, int out_size) {
    const float* x    = (const float*)d_in[0];
    const float* wih  = (const float*)d_in[1];
    const float* whh  = (const float*)d_in[2];
    const float* bih  = (const float*)d_in[3];
    const float* bhh  = (const float*)d_in[4];
    const float* wsum = (const float*)d_in[5];
    const float* bsum = (const float*)d_in[6];
    const float* wcar = (const float*)d_in[7];
    const float* bcar = (const float*)d_in[8];
    float* out = (float*)d_out;
    gru_adder_kernel<<<GRID_BLOCKS, NTHREADS>>>(x, wih, whh, bih, bhh,
                                                wsum, bsum, wcar, bcar, out);
}